// round 1
// baseline (speedup 1.0000x reference)
#include <cuda_runtime.h>

// ---------------------------------------------------------------------------
// GQA: B=4, S=2048, E=1024, H=16, G=4, HPG=4, HD=64, KV_DIM=256
// Pipeline: QKV SGEMMs -> flash attention (permuted output) -> output SGEMM
// All fp32 (rel_err budget 1e-3 too tight for naive bf16; tf32 deferred).
// ---------------------------------------------------------------------------

#define B_   4
#define S_   2048
#define E_   1024
#define H_   16
#define G_   4
#define HPG_ 4
#define HD_  64
#define KV_  256
#define M_   (B_ * S_)      // 8192 rows

// Scratch (allocation-free rule: __device__ globals)
__device__ float g_Q[(size_t)M_ * E_];   // 33.5 MB
__device__ float g_K[(size_t)M_ * KV_];  //  8.4 MB
__device__ float g_V[(size_t)M_ * KV_];  //  8.4 MB
__device__ float g_A[(size_t)M_ * E_];   // 33.5 MB (attention out, permuted)

// ---------------------------------------------------------------------------
// SGEMM: C[M,N] = A[M,K] @ W[K,N] + bias[N]
// 128x128 block tile, BK=8, 256 threads, 8x8 per-thread fragment.
// Requires M%128==0, N%128==0, K%8==0 (true for all launches here).
// ---------------------------------------------------------------------------
__global__ __launch_bounds__(256) void sgemm_bias(
    const float* __restrict__ A, const float* __restrict__ W,
    const float* __restrict__ bias, float* __restrict__ C,
    int M, int N, int K)
{
    __shared__ float As[8][128];   // [k][row] (A transposed in smem)
    __shared__ float Bs[8][128];   // [k][col]

    const int tid  = threadIdx.x;
    const int tr   = tid >> 4;     // 0..15
    const int tc   = tid & 15;     // 0..15
    const int row0 = blockIdx.y * 128;
    const int col0 = blockIdx.x * 128;

    const int a_row = tid >> 1;          // 0..127
    const int a_k   = (tid & 1) * 4;     // 0 or 4
    const int b_k   = tid >> 5;          // 0..7
    const int b_col = (tid & 31) * 4;    // 0..124

    const float* Ap = A + (size_t)(row0 + a_row) * K + a_k;
    const float* Wp = W + (size_t)b_k * N + col0 + b_col;

    float acc[8][8];
#pragma unroll
    for (int i = 0; i < 8; i++)
#pragma unroll
        for (int j = 0; j < 8; j++) acc[i][j] = 0.0f;

    for (int k0 = 0; k0 < K; k0 += 8) {
        float4 av = *reinterpret_cast<const float4*>(Ap + k0);
        float4 bv = *reinterpret_cast<const float4*>(Wp + (size_t)k0 * N);
        As[a_k + 0][a_row] = av.x;
        As[a_k + 1][a_row] = av.y;
        As[a_k + 2][a_row] = av.z;
        As[a_k + 3][a_row] = av.w;
        *reinterpret_cast<float4*>(&Bs[b_k][b_col]) = bv;
        __syncthreads();

#pragma unroll
        for (int k = 0; k < 8; k++) {
            float4 a0 = *reinterpret_cast<const float4*>(&As[k][tr * 4]);
            float4 a1 = *reinterpret_cast<const float4*>(&As[k][64 + tr * 4]);
            float4 b0 = *reinterpret_cast<const float4*>(&Bs[k][tc * 4]);
            float4 b1 = *reinterpret_cast<const float4*>(&Bs[k][64 + tc * 4]);
            float a[8] = {a0.x, a0.y, a0.z, a0.w, a1.x, a1.y, a1.z, a1.w};
            float b[8] = {b0.x, b0.y, b0.z, b0.w, b1.x, b1.y, b1.z, b1.w};
#pragma unroll
            for (int i = 0; i < 8; i++)
#pragma unroll
                for (int j = 0; j < 8; j++)
                    acc[i][j] += a[i] * b[j];
        }
        __syncthreads();
    }

#pragma unroll
    for (int ih = 0; ih < 2; ih++) {
#pragma unroll
        for (int i = 0; i < 4; i++) {
            int r = row0 + ih * 64 + tr * 4 + i;
#pragma unroll
            for (int jh = 0; jh < 2; jh++) {
                int c = col0 + jh * 64 + tc * 4;
                float4 v;
                v.x = acc[ih * 4 + i][jh * 4 + 0] + bias[c + 0];
                v.y = acc[ih * 4 + i][jh * 4 + 1] + bias[c + 1];
                v.z = acc[ih * 4 + i][jh * 4 + 2] + bias[c + 2];
                v.w = acc[ih * 4 + i][jh * 4 + 3] + bias[c + 3];
                *reinterpret_cast<float4*>(&C[(size_t)r * N + c]) = v;
            }
        }
    }
}

// ---------------------------------------------------------------------------
// Flash attention, fp32. Grid: (S/64, B*16). blockIdx.y = b*16 + g*4 + p.
// 64-query x 64-key tiles, 256 threads (16x16), 4x4 fragments.
// Output written in the (HPG, G, hd) permuted order -> g_A is GEMM-ready.
// ---------------------------------------------------------------------------
#define PADW 68   // smem row stride (floats): 16B-aligned, kills bank conflicts

__global__ __launch_bounds__(256) void attn_kernel(
    const float* __restrict__ Qg, const float* __restrict__ Kg,
    const float* __restrict__ Vg, float* __restrict__ Ag)
{
    extern __shared__ float sm[];
    float (*Qs)[PADW] = (float(*)[PADW])(sm);                 // [row][d], pre-scaled
    float (*Kt)[PADW] = (float(*)[PADW])(sm + 64 * PADW);     // [d][col] (transposed)
    float (*Vs)[PADW] = (float(*)[PADW])(sm + 2 * 64 * PADW); // [col][d]
    float (*Ps)[PADW] = (float(*)[PADW])(sm + 3 * 64 * PADW); // [row][k]

    const int tid = threadIdx.x;
    const int ty  = tid >> 4;   // 0..15: query-row group
    const int tx  = tid & 15;   // 0..15: key-col / d-col group
    const int q0  = blockIdx.x * 64;
    const int head = blockIdx.y;
    const int b = head >> 4;
    const int g = (head >> 2) & 3;
    const int p = head & 3;
    const int h = (g << 2) + p;         // Q head index = g*HPG + p

    // Load Q tile, folding in 1/sqrt(64)
#pragma unroll
    for (int i = 0; i < 4; i++) {
        int idx = tid + i * 256;
        int r = idx >> 4;
        int d = (idx & 15) << 2;
        float4 v = *reinterpret_cast<const float4*>(
            Qg + (size_t)(b * S_ + q0 + r) * E_ + h * HD_ + d);
        v.x *= 0.125f; v.y *= 0.125f; v.z *= 0.125f; v.w *= 0.125f;
        *reinterpret_cast<float4*>(&Qs[r][d]) = v;
    }

    float acc[4][4];
    float m_i[4], l_i[4];
#pragma unroll
    for (int i = 0; i < 4; i++) {
        m_i[i] = -1e30f;
        l_i[i] = 0.0f;
#pragma unroll
        for (int j = 0; j < 4; j++) acc[i][j] = 0.0f;
    }

    for (int kv0 = 0; kv0 < S_; kv0 += 64) {
        __syncthreads();   // prev iter done with Kt/Vs/Ps (also covers Qs on iter 0)

        // Load K (transposed into [d][col]) and V tiles. KV head index = g.
#pragma unroll
        for (int i = 0; i < 4; i++) {
            int idx = tid + i * 256;
            int c = idx >> 4;
            int d = (idx & 15) << 2;
            size_t base = (size_t)(b * S_ + kv0 + c) * KV_ + g * HD_ + d;
            float4 kvv = *reinterpret_cast<const float4*>(Kg + base);
            Kt[d + 0][c] = kvv.x;
            Kt[d + 1][c] = kvv.y;
            Kt[d + 2][c] = kvv.z;
            Kt[d + 3][c] = kvv.w;
            float4 vv = *reinterpret_cast<const float4*>(Vg + base);
            *reinterpret_cast<float4*>(&Vs[c][d]) = vv;
        }
        __syncthreads();

        // S = (Q*scale) @ K^T for this thread's 4x4 fragment
        float s[4][4];
#pragma unroll
        for (int i = 0; i < 4; i++)
#pragma unroll
            for (int j = 0; j < 4; j++) s[i][j] = 0.0f;

#pragma unroll 4
        for (int d0 = 0; d0 < 64; d0 += 4) {
            float a[4][4], bb[4][4];
#pragma unroll
            for (int i = 0; i < 4; i++)
                *reinterpret_cast<float4*>(a[i]) =
                    *reinterpret_cast<const float4*>(&Qs[ty * 4 + i][d0]);
#pragma unroll
            for (int dd = 0; dd < 4; dd++)
                *reinterpret_cast<float4*>(bb[dd]) =
                    *reinterpret_cast<const float4*>(&Kt[d0 + dd][tx * 4]);
#pragma unroll
            for (int i = 0; i < 4; i++)
#pragma unroll
                for (int dd = 0; dd < 4; dd++)
#pragma unroll
                    for (int j = 0; j < 4; j++)
                        s[i][j] += a[i][dd] * bb[dd][j];
        }

        // Online softmax per row (16 tx lanes share each row; width-16 shuffles)
#pragma unroll
        for (int i = 0; i < 4; i++) {
            float rmax = fmaxf(fmaxf(s[i][0], s[i][1]), fmaxf(s[i][2], s[i][3]));
#pragma unroll
            for (int off = 8; off > 0; off >>= 1)
                rmax = fmaxf(rmax, __shfl_xor_sync(0xffffffffu, rmax, off, 16));
            float newm = fmaxf(m_i[i], rmax);
            float corr = __expf(m_i[i] - newm);
            float rsum = 0.0f;
#pragma unroll
            for (int j = 0; j < 4; j++) {
                s[i][j] = __expf(s[i][j] - newm);
                rsum += s[i][j];
            }
#pragma unroll
            for (int off = 8; off > 0; off >>= 1)
                rsum += __shfl_xor_sync(0xffffffffu, rsum, off, 16);
            m_i[i] = newm;
            l_i[i] = l_i[i] * corr + rsum;
#pragma unroll
            for (int j = 0; j < 4; j++) acc[i][j] *= corr;
            *reinterpret_cast<float4*>(&Ps[ty * 4 + i][tx * 4]) =
                *reinterpret_cast<float4*>(s[i]);
        }
        __syncthreads();

        // O += P @ V  (this thread: rows ty*4.., d-cols tx*4..)
#pragma unroll 4
        for (int k0 = 0; k0 < 64; k0 += 4) {
            float a[4][4], bb[4][4];
#pragma unroll
            for (int i = 0; i < 4; i++)
                *reinterpret_cast<float4*>(a[i]) =
                    *reinterpret_cast<const float4*>(&Ps[ty * 4 + i][k0]);
#pragma unroll
            for (int kk = 0; kk < 4; kk++)
                *reinterpret_cast<float4*>(bb[kk]) =
                    *reinterpret_cast<const float4*>(&Vs[k0 + kk][tx * 4]);
#pragma unroll
            for (int i = 0; i < 4; i++)
#pragma unroll
                for (int kk = 0; kk < 4; kk++)
#pragma unroll
                    for (int j = 0; j < 4; j++)
                        acc[i][j] += a[i][kk] * bb[kk][j];
        }
    }

    // Normalize and store in (HPG, G, hd) order: col = p*256 + g*64 + d
#pragma unroll
    for (int i = 0; i < 4; i++) {
        float inv = 1.0f / l_i[i];
        int r = q0 + ty * 4 + i;
        float4 v;
        v.x = acc[i][0] * inv;
        v.y = acc[i][1] * inv;
        v.z = acc[i][2] * inv;
        v.w = acc[i][3] * inv;
        *reinterpret_cast<float4*>(
            Ag + (size_t)(b * S_ + r) * E_ + p * (G_ * HD_) + g * HD_ + tx * 4) = v;
    }
}

// ---------------------------------------------------------------------------
// Launch
// ---------------------------------------------------------------------------
extern "C" void kernel_launch(void* const* d_in, const int* in_sizes, int n_in,
                              void* d_out, int out_size)
{
    const float* x  = (const float*)d_in[0];
    const float* Wq = (const float*)d_in[1];
    const float* bq = (const float*)d_in[2];
    const float* Wk = (const float*)d_in[3];
    const float* bk = (const float*)d_in[4];
    const float* Wv = (const float*)d_in[5];
    const float* bv = (const float*)d_in[6];
    const float* Wo = (const float*)d_in[7];
    const float* bo = (const float*)d_in[8];
    float* out = (float*)d_out;

    float *Qp, *Kp, *Vp, *Ap;
    cudaGetSymbolAddress((void**)&Qp, g_Q);
    cudaGetSymbolAddress((void**)&Kp, g_K);
    cudaGetSymbolAddress((void**)&Vp, g_V);
    cudaGetSymbolAddress((void**)&Ap, g_A);

    const int smem_attn = 4 * 64 * PADW * (int)sizeof(float);  // 69632 B
    cudaFuncSetAttribute((const void*)attn_kernel,
                         cudaFuncAttributeMaxDynamicSharedMemorySize, smem_attn);

    dim3 blk(256);
    // QKV projections
    sgemm_bias<<<dim3(E_ / 128, M_ / 128), blk>>>(x, Wq, bq, Qp, M_, E_, E_);
    sgemm_bias<<<dim3(KV_ / 128, M_ / 128), blk>>>(x, Wk, bk, Kp, M_, KV_, E_);
    sgemm_bias<<<dim3(KV_ / 128, M_ / 128), blk>>>(x, Wv, bv, Vp, M_, KV_, E_);
    // Attention (writes permuted layout)
    attn_kernel<<<dim3(S_ / 64, B_ * H_), blk, smem_attn>>>(Qp, Kp, Vp, Ap);
    // Output projection
    sgemm_bias<<<dim3(E_ / 128, M_ / 128), blk>>>(Ap, Wo, bo, out, M_, E_, E_);
}

// round 4
// speedup vs baseline: 2.0664x; 2.0664x over previous
#include <cuda_runtime.h>
#include <cstdint>

// ---------------------------------------------------------------------------
// GQA: B=4, S=2048, E=1024, H=16, G=4, HPG=4, HD=64, KV_DIM=256
// Round 4 (tf32 resubmit #2 after broker failures): all GEMM work on tf32
// mma.sync.m16n8k8 with cvt.rna rounding.
// ---------------------------------------------------------------------------

#define B_   4
#define S_   2048
#define E_   1024
#define G_   4
#define HD_  64
#define KV_  256
#define M_   (B_ * S_)

// Scratch (allocation-free rule: __device__ globals)
__device__ float g_Q[(size_t)M_ * E_];
__device__ float g_K[(size_t)M_ * KV_];
__device__ float g_V[(size_t)M_ * KV_];
__device__ float g_A[(size_t)M_ * E_];

__device__ __forceinline__ unsigned f2tf(float x) {
    unsigned r;
    asm("cvt.rna.tf32.f32 %0, %1;" : "=r"(r) : "f"(x));
    return r;
}

__device__ __forceinline__ void mma_tf32(float* c, const unsigned* a, const unsigned* b) {
    asm volatile(
        "mma.sync.aligned.m16n8k8.row.col.f32.tf32.tf32.f32 "
        "{%0,%1,%2,%3}, {%4,%5,%6,%7}, {%8,%9}, {%0,%1,%2,%3};\n"
        : "+f"(c[0]), "+f"(c[1]), "+f"(c[2]), "+f"(c[3])
        : "r"(a[0]), "r"(a[1]), "r"(a[2]), "r"(a[3]),
          "r"(b[0]), "r"(b[1]));
}

// ---------------------------------------------------------------------------
// tf32 GEMM: C[M,N] = A[M,K] @ W[K,N] + bias[N]
// 128x128 block, BK=32, 256 threads = 8 warps (2m x 4n), warp tile 64x32.
// smem stride 136 words -> conflict-free fragment loads.
// ---------------------------------------------------------------------------
#define GSTR 136

__global__ __launch_bounds__(256) void gemm_tf32(
    const float* __restrict__ A, const float* __restrict__ W,
    const float* __restrict__ bias, float* __restrict__ C,
    int M, int N, int K)
{
    __shared__ unsigned As[32][GSTR];   // [k][m]
    __shared__ unsigned Bs[32][GSTR];   // [k][n]

    const int tid  = threadIdx.x;
    const int lane = tid & 31;
    const int warp = tid >> 5;
    const int gid  = lane >> 2;     // 0..7
    const int tg   = lane & 3;      // 0..3
    const int wm0  = (warp >> 2) * 64;
    const int wn0  = (warp & 3) * 32;
    const int row0 = blockIdx.y * 128;
    const int col0 = blockIdx.x * 128;

    // Global-load assignments
    const int arow  = tid >> 1;          // 0..127
    const int acol0 = (tid & 1) * 16;    // 0 or 16
    const int bkr   = tid >> 5;          // 0..7 (k row base, step 8)
    const int bc4   = tid & 31;          // float4 column 0..31

    const float* Abase = A + (size_t)(row0 + arow) * K + acol0;
    const float* Wbase = W + (size_t)bkr * N + col0 + bc4 * 4;

    float4 pa[4], pb[4];

    // prefetch k0 = 0
#pragma unroll
    for (int i = 0; i < 4; i++) pa[i] = *(const float4*)(Abase + i * 4);
#pragma unroll
    for (int j = 0; j < 4; j++) pb[j] = *(const float4*)(Wbase + (size_t)(8 * j) * N);

    // store tile 0
#pragma unroll
    for (int i = 0; i < 4; i++) {
        As[acol0 + i * 4 + 0][arow] = f2tf(pa[i].x);
        As[acol0 + i * 4 + 1][arow] = f2tf(pa[i].y);
        As[acol0 + i * 4 + 2][arow] = f2tf(pa[i].z);
        As[acol0 + i * 4 + 3][arow] = f2tf(pa[i].w);
    }
#pragma unroll
    for (int j = 0; j < 4; j++) {
        unsigned* dst = &Bs[bkr + 8 * j][bc4 * 4];
        dst[0] = f2tf(pb[j].x); dst[1] = f2tf(pb[j].y);
        dst[2] = f2tf(pb[j].z); dst[3] = f2tf(pb[j].w);
    }
    __syncthreads();

    float acc[4][4][4];
#pragma unroll
    for (int mt = 0; mt < 4; mt++)
#pragma unroll
        for (int nt = 0; nt < 4; nt++)
#pragma unroll
            for (int r = 0; r < 4; r++) acc[mt][nt][r] = 0.0f;

    for (int k0 = 0; k0 < K; k0 += 32) {
        const bool has_next = (k0 + 32) < K;
        if (has_next) {
#pragma unroll
            for (int i = 0; i < 4; i++)
                pa[i] = *(const float4*)(Abase + (k0 + 32) + i * 4);
#pragma unroll
            for (int j = 0; j < 4; j++)
                pb[j] = *(const float4*)(Wbase + (size_t)(k0 + 32 + 8 * j) * N);
        }

#pragma unroll
        for (int ks = 0; ks < 4; ks++) {
            unsigned a[4][4];
            unsigned b[4][2];
#pragma unroll
            for (int mt = 0; mt < 4; mt++) {
                int m = wm0 + mt * 16 + gid;
                a[mt][0] = As[ks * 8 + tg][m];
                a[mt][1] = As[ks * 8 + tg][m + 8];
                a[mt][2] = As[ks * 8 + tg + 4][m];
                a[mt][3] = As[ks * 8 + tg + 4][m + 8];
            }
#pragma unroll
            for (int nt = 0; nt < 4; nt++) {
                b[nt][0] = Bs[ks * 8 + tg][wn0 + nt * 8 + gid];
                b[nt][1] = Bs[ks * 8 + tg + 4][wn0 + nt * 8 + gid];
            }
#pragma unroll
            for (int mt = 0; mt < 4; mt++)
#pragma unroll
                for (int nt = 0; nt < 4; nt++)
                    mma_tf32(acc[mt][nt], a[mt], b[nt]);
        }
        __syncthreads();

        if (has_next) {
#pragma unroll
            for (int i = 0; i < 4; i++) {
                As[acol0 + i * 4 + 0][arow] = f2tf(pa[i].x);
                As[acol0 + i * 4 + 1][arow] = f2tf(pa[i].y);
                As[acol0 + i * 4 + 2][arow] = f2tf(pa[i].z);
                As[acol0 + i * 4 + 3][arow] = f2tf(pa[i].w);
            }
#pragma unroll
            for (int j = 0; j < 4; j++) {
                unsigned* dst = &Bs[bkr + 8 * j][bc4 * 4];
                dst[0] = f2tf(pb[j].x); dst[1] = f2tf(pb[j].y);
                dst[2] = f2tf(pb[j].z); dst[3] = f2tf(pb[j].w);
            }
            __syncthreads();
        }
    }

    // Epilogue: bias + store (float2 per fragment row)
#pragma unroll
    for (int mt = 0; mt < 4; mt++) {
        int r0 = row0 + wm0 + mt * 16 + gid;
#pragma unroll
        for (int nt = 0; nt < 4; nt++) {
            int c = col0 + wn0 + nt * 8 + 2 * tg;
            float bx = bias[c], by = bias[c + 1];
            float2 v0 = make_float2(acc[mt][nt][0] + bx, acc[mt][nt][1] + by);
            float2 v1 = make_float2(acc[mt][nt][2] + bx, acc[mt][nt][3] + by);
            *(float2*)&C[(size_t)r0 * N + c]       = v0;
            *(float2*)&C[(size_t)(r0 + 8) * N + c] = v1;
        }
    }
}

// ---------------------------------------------------------------------------
// Flash attention on tf32 mma. 128 threads (4 warps), 64 q-rows per block
// (warp w owns rows w*16..w*16+15), 64-key tiles, head_dim 64.
// Grid: (S/64, B*16); blockIdx.y = b*16 + grp*4 + p.
// Output written permuted: col = p*256 + grp*64 + d  -> g_A GEMM-ready.
// ---------------------------------------------------------------------------
#define QSTR 68
#define KSTR 72

__global__ __launch_bounds__(128) void attn_tf32(
    const float* __restrict__ Qg, const float* __restrict__ Kg,
    const float* __restrict__ Vg, float* __restrict__ Ag)
{
    extern __shared__ unsigned smx[];
    unsigned (*Qs)[QSTR] = (unsigned(*)[QSTR])(smx);                          // [q][d]
    unsigned (*Ks)[KSTR] = (unsigned(*)[KSTR])(smx + 64 * QSTR);              // [d][key]
    unsigned (*Vs)[KSTR] = (unsigned(*)[KSTR])(smx + 64 * QSTR + 64 * KSTR);  // [key][d]
    unsigned (*Ps)[QSTR] = (unsigned(*)[QSTR])(smx + 64 * QSTR + 128 * KSTR); // [q][key]

    const int tid  = threadIdx.x;
    const int lane = tid & 31;
    const int warp = tid >> 5;
    const int gid  = lane >> 2;
    const int tg   = lane & 3;
    const int wq0  = warp * 16;

    const int q0   = blockIdx.x * 64;
    const int head = blockIdx.y;
    const int b    = head >> 4;
    const int grp  = (head >> 2) & 3;
    const int p    = head & 3;
    const int h    = grp * 4 + p;

    // Load Q tile (scaled by 1/sqrt(64), tf32-rounded)
#pragma unroll
    for (int i = 0; i < 8; i++) {
        int idx = tid + 128 * i;
        int r = idx >> 4;
        int d = (idx & 15) * 4;
        float4 v = *(const float4*)(Qg + (size_t)(b * S_ + q0 + r) * E_ + h * HD_ + d);
        unsigned* dst = &Qs[r][d];
        dst[0] = f2tf(v.x * 0.125f); dst[1] = f2tf(v.y * 0.125f);
        dst[2] = f2tf(v.z * 0.125f); dst[3] = f2tf(v.w * 0.125f);
    }

    float oacc[8][4];
#pragma unroll
    for (int nt = 0; nt < 8; nt++)
#pragma unroll
        for (int r = 0; r < 4; r++) oacc[nt][r] = 0.0f;
    float m0 = -1e30f, m1 = -1e30f, l0 = 0.0f, l1 = 0.0f;

    for (int kv0 = 0; kv0 < S_; kv0 += 64) {
        __syncthreads();   // protect Ks/Vs (and Qs on iter 0)

        // Load K (transposed -> [d][key]) and V ([key][d]) for kv head = grp
#pragma unroll
        for (int i = 0; i < 8; i++) {
            int idx = tid + 128 * i;
            int c = idx >> 4;            // key within tile
            int d = (idx & 15) * 4;
            size_t base = (size_t)(b * S_ + kv0 + c) * KV_ + grp * HD_ + d;
            float4 kv = *(const float4*)(Kg + base);
            Ks[d + 0][c] = f2tf(kv.x);
            Ks[d + 1][c] = f2tf(kv.y);
            Ks[d + 2][c] = f2tf(kv.z);
            Ks[d + 3][c] = f2tf(kv.w);
            float4 vv = *(const float4*)(Vg + base);
            unsigned* dst = &Vs[c][d];
            dst[0] = f2tf(vv.x); dst[1] = f2tf(vv.y);
            dst[2] = f2tf(vv.z); dst[3] = f2tf(vv.w);
        }
        __syncthreads();

        // S = Q @ K^T   (warp: 16 x 64)
        float sacc[8][4];
#pragma unroll
        for (int nt = 0; nt < 8; nt++)
#pragma unroll
            for (int r = 0; r < 4; r++) sacc[nt][r] = 0.0f;

#pragma unroll
        for (int ks = 0; ks < 8; ks++) {
            unsigned a[4];
            a[0] = Qs[wq0 + gid][ks * 8 + tg];
            a[1] = Qs[wq0 + gid + 8][ks * 8 + tg];
            a[2] = Qs[wq0 + gid][ks * 8 + tg + 4];
            a[3] = Qs[wq0 + gid + 8][ks * 8 + tg + 4];
#pragma unroll
            for (int nt = 0; nt < 8; nt++) {
                unsigned bb[2];
                bb[0] = Ks[ks * 8 + tg][nt * 8 + gid];
                bb[1] = Ks[ks * 8 + tg + 4][nt * 8 + gid];
                mma_tf32(sacc[nt], a, bb);
            }
        }

        // Online softmax. Lane owns rows (wq0+gid) [c0,c1] and (wq0+gid+8) [c2,c3].
        float rmax0 = -1e30f, rmax1 = -1e30f;
#pragma unroll
        for (int nt = 0; nt < 8; nt++) {
            rmax0 = fmaxf(rmax0, fmaxf(sacc[nt][0], sacc[nt][1]));
            rmax1 = fmaxf(rmax1, fmaxf(sacc[nt][2], sacc[nt][3]));
        }
        rmax0 = fmaxf(rmax0, __shfl_xor_sync(0xffffffffu, rmax0, 1));
        rmax0 = fmaxf(rmax0, __shfl_xor_sync(0xffffffffu, rmax0, 2));
        rmax1 = fmaxf(rmax1, __shfl_xor_sync(0xffffffffu, rmax1, 1));
        rmax1 = fmaxf(rmax1, __shfl_xor_sync(0xffffffffu, rmax1, 2));

        float nm0 = fmaxf(m0, rmax0), nm1 = fmaxf(m1, rmax1);
        float corr0 = __expf(m0 - nm0), corr1 = __expf(m1 - nm1);
        float sum0 = 0.0f, sum1 = 0.0f;

#pragma unroll
        for (int nt = 0; nt < 8; nt++) {
            float e0 = __expf(sacc[nt][0] - nm0);
            float e1 = __expf(sacc[nt][1] - nm0);
            float e2 = __expf(sacc[nt][2] - nm1);
            float e3 = __expf(sacc[nt][3] - nm1);
            sum0 += e0 + e1;
            sum1 += e2 + e3;
            Ps[wq0 + gid][nt * 8 + 2 * tg]     = f2tf(e0);
            Ps[wq0 + gid][nt * 8 + 2 * tg + 1] = f2tf(e1);
            Ps[wq0 + gid + 8][nt * 8 + 2 * tg]     = f2tf(e2);
            Ps[wq0 + gid + 8][nt * 8 + 2 * tg + 1] = f2tf(e3);
            oacc[nt][0] *= corr0; oacc[nt][1] *= corr0;
            oacc[nt][2] *= corr1; oacc[nt][3] *= corr1;
        }
        sum0 += __shfl_xor_sync(0xffffffffu, sum0, 1);
        sum0 += __shfl_xor_sync(0xffffffffu, sum0, 2);
        sum1 += __shfl_xor_sync(0xffffffffu, sum1, 1);
        sum1 += __shfl_xor_sync(0xffffffffu, sum1, 2);
        m0 = nm0; m1 = nm1;
        l0 = l0 * corr0 + sum0;
        l1 = l1 * corr1 + sum1;

        __syncwarp();   // Ps visible within warp (rows are warp-private)

        // O += P @ V   (warp: 16 x 64)
#pragma unroll
        for (int ks = 0; ks < 8; ks++) {
            unsigned a[4];
            a[0] = Ps[wq0 + gid][ks * 8 + tg];
            a[1] = Ps[wq0 + gid + 8][ks * 8 + tg];
            a[2] = Ps[wq0 + gid][ks * 8 + tg + 4];
            a[3] = Ps[wq0 + gid + 8][ks * 8 + tg + 4];
#pragma unroll
            for (int nt = 0; nt < 8; nt++) {
                unsigned bb[2];
                bb[0] = Vs[ks * 8 + tg][nt * 8 + gid];
                bb[1] = Vs[ks * 8 + tg + 4][nt * 8 + gid];
                mma_tf32(oacc[nt], a, bb);
            }
        }
    }

    // Normalize + store permuted: col = p*256 + grp*64 + d
    float inv0 = 1.0f / l0, inv1 = 1.0f / l1;
    int r0 = b * S_ + q0 + wq0 + gid;
    int cbase = p * (G_ * HD_) + grp * HD_;
#pragma unroll
    for (int nt = 0; nt < 8; nt++) {
        int c = cbase + nt * 8 + 2 * tg;
        float2 v0 = make_float2(oacc[nt][0] * inv0, oacc[nt][1] * inv0);
        float2 v1 = make_float2(oacc[nt][2] * inv1, oacc[nt][3] * inv1);
        *(float2*)&Ag[(size_t)r0 * E_ + c]       = v0;
        *(float2*)&Ag[(size_t)(r0 + 8) * E_ + c] = v1;
    }
}

// ---------------------------------------------------------------------------
// Launch
// ---------------------------------------------------------------------------
extern "C" void kernel_launch(void* const* d_in, const int* in_sizes, int n_in,
                              void* d_out, int out_size)
{
    const float* x  = (const float*)d_in[0];
    const float* Wq = (const float*)d_in[1];
    const float* bq = (const float*)d_in[2];
    const float* Wk = (const float*)d_in[3];
    const float* bk = (const float*)d_in[4];
    const float* Wv = (const float*)d_in[5];
    const float* bv = (const float*)d_in[6];
    const float* Wo = (const float*)d_in[7];
    const float* bo = (const float*)d_in[8];
    float* out = (float*)d_out;

    float *Qp, *Kp, *Vp, *Ap;
    cudaGetSymbolAddress((void**)&Qp, g_Q);
    cudaGetSymbolAddress((void**)&Kp, g_K);
    cudaGetSymbolAddress((void**)&Vp, g_V);
    cudaGetSymbolAddress((void**)&Ap, g_A);

    const int smem_attn = 64 * (QSTR + KSTR + KSTR + QSTR) * (int)sizeof(unsigned); // 71680
    cudaFuncSetAttribute((const void*)attn_tf32,
                         cudaFuncAttributeMaxDynamicSharedMemorySize, smem_attn);

    // QKV projections
    gemm_tf32<<<dim3(E_ / 128, M_ / 128), 256>>>(x, Wq, bq, Qp, M_, E_, E_);
    gemm_tf32<<<dim3(KV_ / 128, M_ / 128), 256>>>(x, Wk, bk, Kp, M_, KV_, E_);
    gemm_tf32<<<dim3(KV_ / 128, M_ / 128), 256>>>(x, Wv, bv, Vp, M_, KV_, E_);
    // Attention (permuted output)
    attn_tf32<<<dim3(S_ / 64, B_ * 16), 128, smem_attn>>>(Qp, Kp, Vp, Ap);
    // Output projection
    gemm_tf32<<<dim3(E_ / 128, M_ / 128), 256>>>(Ap, Wo, bo, out, M_, E_, E_);
}

// round 5
// speedup vs baseline: 3.0800x; 1.4905x over previous
#include <cuda_runtime.h>
#include <cstdint>

// ---------------------------------------------------------------------------
// GQA: B=4, S=2048, E=1024, H=16, G=4, HPG=4, HD=64, KV_DIM=256
// Round 5: attention rewritten for LDS-traffic reduction:
//   - 32-row warp tiles (128 q-rows per 128-thread block)
//   - K stored natural [key][d] (row.col MMA needs col-major B = natural K)
//   - P stored via STS.64 pairs
// GEMMs unchanged from R4.
// ---------------------------------------------------------------------------

#define B_   4
#define S_   2048
#define E_   1024
#define G_   4
#define HD_  64
#define KV_  256
#define M_   (B_ * S_)

__device__ float g_Q[(size_t)M_ * E_];
__device__ float g_K[(size_t)M_ * KV_];
__device__ float g_V[(size_t)M_ * KV_];
__device__ float g_A[(size_t)M_ * E_];

__device__ __forceinline__ unsigned f2tf(float x) {
    unsigned r;
    asm("cvt.rna.tf32.f32 %0, %1;" : "=r"(r) : "f"(x));
    return r;
}

__device__ __forceinline__ void mma_tf32(float* c, const unsigned* a, const unsigned* b) {
    asm volatile(
        "mma.sync.aligned.m16n8k8.row.col.f32.tf32.tf32.f32 "
        "{%0,%1,%2,%3}, {%4,%5,%6,%7}, {%8,%9}, {%0,%1,%2,%3};\n"
        : "+f"(c[0]), "+f"(c[1]), "+f"(c[2]), "+f"(c[3])
        : "r"(a[0]), "r"(a[1]), "r"(a[2]), "r"(a[3]),
          "r"(b[0]), "r"(b[1]));
}

// ---------------------------------------------------------------------------
// tf32 GEMM (unchanged from R4): C[M,N] = A[M,K] @ W[K,N] + bias[N]
// ---------------------------------------------------------------------------
#define GSTR 136

__global__ __launch_bounds__(256) void gemm_tf32(
    const float* __restrict__ A, const float* __restrict__ W,
    const float* __restrict__ bias, float* __restrict__ C,
    int M, int N, int K)
{
    __shared__ unsigned As[32][GSTR];
    __shared__ unsigned Bs[32][GSTR];

    const int tid  = threadIdx.x;
    const int lane = tid & 31;
    const int warp = tid >> 5;
    const int gid  = lane >> 2;
    const int tg   = lane & 3;
    const int wm0  = (warp >> 2) * 64;
    const int wn0  = (warp & 3) * 32;
    const int row0 = blockIdx.y * 128;
    const int col0 = blockIdx.x * 128;

    const int arow  = tid >> 1;
    const int acol0 = (tid & 1) * 16;
    const int bkr   = tid >> 5;
    const int bc4   = tid & 31;

    const float* Abase = A + (size_t)(row0 + arow) * K + acol0;
    const float* Wbase = W + (size_t)bkr * N + col0 + bc4 * 4;

    float4 pa[4], pb[4];

#pragma unroll
    for (int i = 0; i < 4; i++) pa[i] = *(const float4*)(Abase + i * 4);
#pragma unroll
    for (int j = 0; j < 4; j++) pb[j] = *(const float4*)(Wbase + (size_t)(8 * j) * N);

#pragma unroll
    for (int i = 0; i < 4; i++) {
        As[acol0 + i * 4 + 0][arow] = f2tf(pa[i].x);
        As[acol0 + i * 4 + 1][arow] = f2tf(pa[i].y);
        As[acol0 + i * 4 + 2][arow] = f2tf(pa[i].z);
        As[acol0 + i * 4 + 3][arow] = f2tf(pa[i].w);
    }
#pragma unroll
    for (int j = 0; j < 4; j++) {
        unsigned* dst = &Bs[bkr + 8 * j][bc4 * 4];
        dst[0] = f2tf(pb[j].x); dst[1] = f2tf(pb[j].y);
        dst[2] = f2tf(pb[j].z); dst[3] = f2tf(pb[j].w);
    }
    __syncthreads();

    float acc[4][4][4];
#pragma unroll
    for (int mt = 0; mt < 4; mt++)
#pragma unroll
        for (int nt = 0; nt < 4; nt++)
#pragma unroll
            for (int r = 0; r < 4; r++) acc[mt][nt][r] = 0.0f;

    for (int k0 = 0; k0 < K; k0 += 32) {
        const bool has_next = (k0 + 32) < K;
        if (has_next) {
#pragma unroll
            for (int i = 0; i < 4; i++)
                pa[i] = *(const float4*)(Abase + (k0 + 32) + i * 4);
#pragma unroll
            for (int j = 0; j < 4; j++)
                pb[j] = *(const float4*)(Wbase + (size_t)(k0 + 32 + 8 * j) * N);
        }

#pragma unroll
        for (int ks = 0; ks < 4; ks++) {
            unsigned a[4][4];
            unsigned b[4][2];
#pragma unroll
            for (int mt = 0; mt < 4; mt++) {
                int m = wm0 + mt * 16 + gid;
                a[mt][0] = As[ks * 8 + tg][m];
                a[mt][1] = As[ks * 8 + tg][m + 8];
                a[mt][2] = As[ks * 8 + tg + 4][m];
                a[mt][3] = As[ks * 8 + tg + 4][m + 8];
            }
#pragma unroll
            for (int nt = 0; nt < 4; nt++) {
                b[nt][0] = Bs[ks * 8 + tg][wn0 + nt * 8 + gid];
                b[nt][1] = Bs[ks * 8 + tg + 4][wn0 + nt * 8 + gid];
            }
#pragma unroll
            for (int mt = 0; mt < 4; mt++)
#pragma unroll
                for (int nt = 0; nt < 4; nt++)
                    mma_tf32(acc[mt][nt], a[mt], b[nt]);
        }
        __syncthreads();

        if (has_next) {
#pragma unroll
            for (int i = 0; i < 4; i++) {
                As[acol0 + i * 4 + 0][arow] = f2tf(pa[i].x);
                As[acol0 + i * 4 + 1][arow] = f2tf(pa[i].y);
                As[acol0 + i * 4 + 2][arow] = f2tf(pa[i].z);
                As[acol0 + i * 4 + 3][arow] = f2tf(pa[i].w);
            }
#pragma unroll
            for (int j = 0; j < 4; j++) {
                unsigned* dst = &Bs[bkr + 8 * j][bc4 * 4];
                dst[0] = f2tf(pb[j].x); dst[1] = f2tf(pb[j].y);
                dst[2] = f2tf(pb[j].z); dst[3] = f2tf(pb[j].w);
            }
            __syncthreads();
        }
    }

#pragma unroll
    for (int mt = 0; mt < 4; mt++) {
        int r0 = row0 + wm0 + mt * 16 + gid;
#pragma unroll
        for (int nt = 0; nt < 4; nt++) {
            int c = col0 + wn0 + nt * 8 + 2 * tg;
            float bx = bias[c], by = bias[c + 1];
            float2 v0 = make_float2(acc[mt][nt][0] + bx, acc[mt][nt][1] + by);
            float2 v1 = make_float2(acc[mt][nt][2] + bx, acc[mt][nt][3] + by);
            *(float2*)&C[(size_t)r0 * N + c]       = v0;
            *(float2*)&C[(size_t)(r0 + 8) * N + c] = v1;
        }
    }
}

// ---------------------------------------------------------------------------
// Flash attention, tf32 mma, LDS-optimized.
// 128 threads (4 warps). Block covers 128 q-rows; warp w covers rows
// w*32..w*32+31 (2 m-tiles of 16). 64-key tiles.
// K and V both stored natural [key][d] in smem (row.col MMA B = col-major).
// Grid: (S/128, B*16); blockIdx.y = b*16 + grp*4 + p.
// Output permuted: col = p*256 + grp*64 + d.
// ---------------------------------------------------------------------------
#define QROWS 128
#define QSTR  68
#define KSTR  72

__global__ __launch_bounds__(128) void attn_tf32(
    const float* __restrict__ Qg, const float* __restrict__ Kg,
    const float* __restrict__ Vg, float* __restrict__ Ag)
{
    extern __shared__ unsigned smx[];
    unsigned (*Qs)[QSTR] = (unsigned(*)[QSTR])(smx);                               // [128][68]
    unsigned (*Ks)[KSTR] = (unsigned(*)[KSTR])(smx + QROWS * QSTR);                // [key][d]
    unsigned (*Vs)[KSTR] = (unsigned(*)[KSTR])(smx + QROWS * QSTR + 64 * KSTR);    // [key][d]
    unsigned (*Ps)[QSTR] = (unsigned(*)[QSTR])(smx + QROWS * QSTR + 128 * KSTR);   // [q][key]

    const int tid  = threadIdx.x;
    const int lane = tid & 31;
    const int warp = tid >> 5;
    const int gid  = lane >> 2;
    const int tg   = lane & 3;
    const int wq0  = warp * 32;

    const int q0   = blockIdx.x * QROWS;
    const int head = blockIdx.y;
    const int b    = head >> 4;
    const int grp  = (head >> 2) & 3;
    const int p    = head & 3;
    const int h    = grp * 4 + p;

    // Load Q tile: 128 rows x 64 d, scaled by 1/8, tf32-rounded.
#pragma unroll
    for (int i = 0; i < 16; i++) {
        int idx = tid + 128 * i;
        int r = idx >> 4;
        int d = (idx & 15) * 4;
        float4 v = *(const float4*)(Qg + (size_t)(b * S_ + q0 + r) * E_ + h * HD_ + d);
        uint4 t;
        t.x = f2tf(v.x * 0.125f); t.y = f2tf(v.y * 0.125f);
        t.z = f2tf(v.z * 0.125f); t.w = f2tf(v.w * 0.125f);
        *(uint4*)&Qs[r][d] = t;
    }

    float oacc[2][8][4];
#pragma unroll
    for (int mt = 0; mt < 2; mt++)
#pragma unroll
        for (int nt = 0; nt < 8; nt++)
#pragma unroll
            for (int r = 0; r < 4; r++) oacc[mt][nt][r] = 0.0f;

    float mrow[2][2], lrow[2][2];
#pragma unroll
    for (int mt = 0; mt < 2; mt++) {
        mrow[mt][0] = -1e30f; mrow[mt][1] = -1e30f;
        lrow[mt][0] = 0.0f;   lrow[mt][1] = 0.0f;
    }

    for (int kv0 = 0; kv0 < S_; kv0 += 64) {
        __syncthreads();   // previous tile done with Ks/Vs/Ps (Qs on iter 0)

        // Fill K and V tiles, both natural [key][d], vectorized STS.128.
#pragma unroll
        for (int i = 0; i < 8; i++) {
            int idx = tid + 128 * i;
            int c = idx >> 4;            // key 0..63
            int d = (idx & 15) * 4;
            size_t base = (size_t)(b * S_ + kv0 + c) * KV_ + grp * HD_ + d;
            float4 kv = *(const float4*)(Kg + base);
            uint4 tk;
            tk.x = f2tf(kv.x); tk.y = f2tf(kv.y); tk.z = f2tf(kv.z); tk.w = f2tf(kv.w);
            *(uint4*)&Ks[c][d] = tk;
            float4 vv = *(const float4*)(Vg + base);
            uint4 tv;
            tv.x = f2tf(vv.x); tv.y = f2tf(vv.y); tv.z = f2tf(vv.z); tv.w = f2tf(vv.w);
            *(uint4*)&Vs[c][d] = tv;
        }
        __syncthreads();

        // ---- S = Q @ K^T : warp tile 32 x 64 ----
        float sacc[2][8][4];
#pragma unroll
        for (int mt = 0; mt < 2; mt++)
#pragma unroll
            for (int nt = 0; nt < 8; nt++)
#pragma unroll
                for (int r = 0; r < 4; r++) sacc[mt][nt][r] = 0.0f;

#pragma unroll
        for (int ks = 0; ks < 8; ks++) {
            unsigned a[2][4];
#pragma unroll
            for (int mt = 0; mt < 2; mt++) {
                int row = wq0 + mt * 16 + gid;
                a[mt][0] = Qs[row][ks * 8 + tg];
                a[mt][1] = Qs[row + 8][ks * 8 + tg];
                a[mt][2] = Qs[row][ks * 8 + tg + 4];
                a[mt][3] = Qs[row + 8][ks * 8 + tg + 4];
            }
            unsigned bb[8][2];
#pragma unroll
            for (int nt = 0; nt < 8; nt++) {
                // B[k][n] with B = K^T: value K[key = nt*8+gid][d = ks*8+tg(+4)]
                bb[nt][0] = Ks[nt * 8 + gid][ks * 8 + tg];
                bb[nt][1] = Ks[nt * 8 + gid][ks * 8 + tg + 4];
            }
#pragma unroll
            for (int mt = 0; mt < 2; mt++)
#pragma unroll
                for (int nt = 0; nt < 8; nt++)
                    mma_tf32(sacc[mt][nt], a[mt], bb[nt]);
        }

        // ---- online softmax (per mt; lane owns rows wq0+mt*16+gid, +8) ----
#pragma unroll
        for (int mt = 0; mt < 2; mt++) {
            float rmax0 = -1e30f, rmax1 = -1e30f;
#pragma unroll
            for (int nt = 0; nt < 8; nt++) {
                rmax0 = fmaxf(rmax0, fmaxf(sacc[mt][nt][0], sacc[mt][nt][1]));
                rmax1 = fmaxf(rmax1, fmaxf(sacc[mt][nt][2], sacc[mt][nt][3]));
            }
            rmax0 = fmaxf(rmax0, __shfl_xor_sync(0xffffffffu, rmax0, 1));
            rmax0 = fmaxf(rmax0, __shfl_xor_sync(0xffffffffu, rmax0, 2));
            rmax1 = fmaxf(rmax1, __shfl_xor_sync(0xffffffffu, rmax1, 1));
            rmax1 = fmaxf(rmax1, __shfl_xor_sync(0xffffffffu, rmax1, 2));

            float nm0 = fmaxf(mrow[mt][0], rmax0);
            float nm1 = fmaxf(mrow[mt][1], rmax1);
            float corr0 = __expf(mrow[mt][0] - nm0);
            float corr1 = __expf(mrow[mt][1] - nm1);
            float sum0 = 0.0f, sum1 = 0.0f;

            int r1 = wq0 + mt * 16 + gid;
#pragma unroll
            for (int nt = 0; nt < 8; nt++) {
                float e0 = __expf(sacc[mt][nt][0] - nm0);
                float e1 = __expf(sacc[mt][nt][1] - nm0);
                float e2 = __expf(sacc[mt][nt][2] - nm1);
                float e3 = __expf(sacc[mt][nt][3] - nm1);
                sum0 += e0 + e1;
                sum1 += e2 + e3;
                uint2 p01 = make_uint2(f2tf(e0), f2tf(e1));
                uint2 p23 = make_uint2(f2tf(e2), f2tf(e3));
                *(uint2*)&Ps[r1][nt * 8 + 2 * tg]     = p01;
                *(uint2*)&Ps[r1 + 8][nt * 8 + 2 * tg] = p23;
                oacc[mt][nt][0] *= corr0; oacc[mt][nt][1] *= corr0;
                oacc[mt][nt][2] *= corr1; oacc[mt][nt][3] *= corr1;
            }
            sum0 += __shfl_xor_sync(0xffffffffu, sum0, 1);
            sum0 += __shfl_xor_sync(0xffffffffu, sum0, 2);
            sum1 += __shfl_xor_sync(0xffffffffu, sum1, 1);
            sum1 += __shfl_xor_sync(0xffffffffu, sum1, 2);
            mrow[mt][0] = nm0; mrow[mt][1] = nm1;
            lrow[mt][0] = lrow[mt][0] * corr0 + sum0;
            lrow[mt][1] = lrow[mt][1] * corr1 + sum1;
        }

        __syncwarp();   // Ps rows are warp-private

        // ---- O += P @ V : warp tile 32 x 64, k = 64 keys ----
#pragma unroll
        for (int ks = 0; ks < 8; ks++) {
            unsigned a[2][4];
#pragma unroll
            for (int mt = 0; mt < 2; mt++) {
                int row = wq0 + mt * 16 + gid;
                a[mt][0] = Ps[row][ks * 8 + tg];
                a[mt][1] = Ps[row + 8][ks * 8 + tg];
                a[mt][2] = Ps[row][ks * 8 + tg + 4];
                a[mt][3] = Ps[row + 8][ks * 8 + tg + 4];
            }
            unsigned bb[8][2];
#pragma unroll
            for (int nt = 0; nt < 8; nt++) {
                // B[k][n] with B = V: value V[key = ks*8+tg(+4)][d = nt*8+gid]
                bb[nt][0] = Vs[ks * 8 + tg][nt * 8 + gid];
                bb[nt][1] = Vs[ks * 8 + tg + 4][nt * 8 + gid];
            }
#pragma unroll
            for (int mt = 0; mt < 2; mt++)
#pragma unroll
                for (int nt = 0; nt < 8; nt++)
                    mma_tf32(oacc[mt][nt], a[mt], bb[nt]);
        }
    }

    // Normalize + store permuted: col = p*256 + grp*64 + d
    const int cbase = p * (G_ * HD_) + grp * HD_;
#pragma unroll
    for (int mt = 0; mt < 2; mt++) {
        float inv0 = 1.0f / lrow[mt][0];
        float inv1 = 1.0f / lrow[mt][1];
        int r0 = b * S_ + q0 + wq0 + mt * 16 + gid;
#pragma unroll
        for (int nt = 0; nt < 8; nt++) {
            int c = cbase + nt * 8 + 2 * tg;
            float2 v0 = make_float2(oacc[mt][nt][0] * inv0, oacc[mt][nt][1] * inv0);
            float2 v1 = make_float2(oacc[mt][nt][2] * inv1, oacc[mt][nt][3] * inv1);
            *(float2*)&Ag[(size_t)r0 * E_ + c]       = v0;
            *(float2*)&Ag[(size_t)(r0 + 8) * E_ + c] = v1;
        }
    }
}

// ---------------------------------------------------------------------------
// Launch
// ---------------------------------------------------------------------------
extern "C" void kernel_launch(void* const* d_in, const int* in_sizes, int n_in,
                              void* d_out, int out_size)
{
    const float* x  = (const float*)d_in[0];
    const float* Wq = (const float*)d_in[1];
    const float* bq = (const float*)d_in[2];
    const float* Wk = (const float*)d_in[3];
    const float* bk = (const float*)d_in[4];
    const float* Wv = (const float*)d_in[5];
    const float* bv = (const float*)d_in[6];
    const float* Wo = (const float*)d_in[7];
    const float* bo = (const float*)d_in[8];
    float* out = (float*)d_out;

    float *Qp, *Kp, *Vp, *Ap;
    cudaGetSymbolAddress((void**)&Qp, g_Q);
    cudaGetSymbolAddress((void**)&Kp, g_K);
    cudaGetSymbolAddress((void**)&Vp, g_V);
    cudaGetSymbolAddress((void**)&Ap, g_A);

    const int smem_attn =
        (QROWS * QSTR + 64 * KSTR + 64 * KSTR + QROWS * QSTR) * (int)sizeof(unsigned); // 106496
    cudaFuncSetAttribute((const void*)attn_tf32,
                         cudaFuncAttributeMaxDynamicSharedMemorySize, smem_attn);

    // QKV projections
    gemm_tf32<<<dim3(E_ / 128, M_ / 128), 256>>>(x, Wq, bq, Qp, M_, E_, E_);
    gemm_tf32<<<dim3(KV_ / 128, M_ / 128), 256>>>(x, Wk, bk, Kp, M_, KV_, E_);
    gemm_tf32<<<dim3(KV_ / 128, M_ / 128), 256>>>(x, Wv, bv, Vp, M_, KV_, E_);
    // Attention (permuted output)
    attn_tf32<<<dim3(S_ / QROWS, B_ * 16), 128, smem_attn>>>(Qp, Kp, Vp, Ap);
    // Output projection
    gemm_tf32<<<dim3(E_ / 128, M_ / 128), 256>>>(Ap, Wo, bo, out, M_, E_, E_);
}